// round 7
// baseline (speedup 1.0000x reference)
#include <cuda_runtime.h>
#include <cstdint>

#define NROWS 256
#define DDIM  768
#define KD    128
#define NK    500
#define TK    4

// output layout (float32, reference return order)
#define OC_OFF  0
#define IDX_OFF 786432
#define SC_OFF  787456
#define QP_OFF  788480

#define NEG_INF (-3.402823466e38f)

__device__ float g_xnT[DDIM * NROWS];      // normalized input, TRANSPOSED [d][row]
__device__ float g_q[NROWS * KD];          // queries
__device__ float g_sc[2][NROWS][NK];       // row/col scores

__device__ __forceinline__ bool better(float a, int ia, float b, int ib) {
    return (a > b) || (a == b && ia < ib);
}

__device__ __forceinline__ void insert4(float* v, int* id, float x, int ix) {
    if (!better(x, ix, v[3], id[3])) return;
    v[3] = x; id[3] = ix;
#pragma unroll
    for (int j = 3; j > 0; j--) {
        if (better(v[j], id[j], v[j - 1], id[j - 1])) {
            float tv = v[j]; v[j] = v[j - 1]; v[j - 1] = tv;
            int   ti = id[j]; id[j] = id[j - 1]; id[j - 1] = ti;
        }
    }
}

// ---------------------------------------------------------------------------
// K0: LayerNorm, one row per block; writes transposed normalized x
// ---------------------------------------------------------------------------
__global__ __launch_bounds__(256) void k0_ln(
    const float* __restrict__ regs,
    const float* __restrict__ gamma,
    const float* __restrict__ beta)
{
    __shared__ float red_s[8], red_q[8];
    __shared__ float s_mu, s_rs;

    const int row = blockIdx.x;
    const int t   = threadIdx.x;
    const int warp = t >> 5, lane = t & 31;

    const float x0 = regs[(size_t)row * DDIM + t];
    const float x1 = regs[(size_t)row * DDIM + t + 256];
    const float x2 = regs[(size_t)row * DDIM + t + 512];

    float s = x0 + x1 + x2;
    float q = x0 * x0 + x1 * x1 + x2 * x2;
#pragma unroll
    for (int o = 16; o; o >>= 1) {
        s += __shfl_xor_sync(0xffffffffu, s, o);
        q += __shfl_xor_sync(0xffffffffu, q, o);
    }
    if (lane == 0) { red_s[warp] = s; red_q[warp] = q; }
    __syncthreads();
    if (t < 32) {
        s = (t < 8) ? red_s[t] : 0.f;
        q = (t < 8) ? red_q[t] : 0.f;
#pragma unroll
        for (int o = 4; o; o >>= 1) {
            s += __shfl_xor_sync(0xffffffffu, s, o);
            q += __shfl_xor_sync(0xffffffffu, q, o);
        }
        if (t == 0) {
            const float mu  = s * (1.0f / DDIM);
            const float var = q * (1.0f / DDIM) - mu * mu;
            s_mu = mu;
            s_rs = rsqrtf(var + 1e-5f);
        }
    }
    __syncthreads();

    const float mu = s_mu, rs = s_rs;
    g_xnT[(size_t)(t      ) * NROWS + row] = (x0 - mu) * rs * gamma[t      ] + beta[t      ];
    g_xnT[(size_t)(t + 256) * NROWS + row] = (x1 - mu) * rs * gamma[t + 256] + beta[t + 256];
    g_xnT[(size_t)(t + 512) * NROWS + row] = (x2 - mu) * rs * gamma[t + 512] + beta[t + 512];
}

// ---------------------------------------------------------------------------
// K1: Q = xn @ Wq + bq, barrier-free mainloop
// grid (8 coltiles of 16, 32 rowtiles of 8), 256 threads
// thread (c4, r, d8): 4 cols x 1 row x 96-deep d slice; smem reduce at end
// ---------------------------------------------------------------------------
__global__ __launch_bounds__(256) void k1_gemm(
    const float* __restrict__ Wq,
    const float* __restrict__ bq)
{
    __shared__ __align__(16) float spart[8][8][16];  // [d8][row][col]

    const int t  = threadIdx.x;
    const int ct = blockIdx.x;     // 0..7  (16 cols)
    const int rt = blockIdx.y;     // 0..31 (8 rows)

    const int c4 = t & 3;
    const int s  = t >> 2;
    const int r  = s & 7;
    const int d8 = s >> 3;          // 0..7: 96-deep d slice

    const float* wp = Wq + (size_t)(d8 * 96) * KD + ct * 16 + c4 * 4;
    const float* xp = g_xnT + (size_t)(d8 * 96) * NROWS + rt * 8 + r;

    float ax = 0.f, ay = 0.f, az = 0.f, aw = 0.f;
#pragma unroll 8
    for (int d = 0; d < 96; d++) {
        const float4 w = *(const float4*)(wp + (size_t)d * KD);
        const float xv = xp[(size_t)d * NROWS];
        ax += xv * w.x; ay += xv * w.y; az += xv * w.z; aw += xv * w.w;
    }
    *(float4*)&spart[d8][r][c4 * 4] = make_float4(ax, ay, az, aw);
    __syncthreads();

    if (t < 128) {
        const int rr = t >> 4, c = t & 15;
        float sum = bq[ct * 16 + c];
#pragma unroll
        for (int k = 0; k < 8; k++) sum += spart[k][rr][c];
        g_q[(size_t)(rt * 8 + rr) * KD + ct * 16 + c] = sum;
    }
}

// ---------------------------------------------------------------------------
// KB: merged scores (blocks 0..127) + query_projected (blocks 128..319)
// ---------------------------------------------------------------------------
__global__ __launch_bounds__(256) void kb_scores_qp(
    const float* __restrict__ row_keys,
    const float* __restrict__ col_keys,
    const float* __restrict__ Wqc,
    const float* __restrict__ bqc,
    float* __restrict__ out)
{
    __shared__ float sk[64][66];   // role A: keys, d-major (transposed)
    __shared__ float sq[32][64];   // role A: q halves
    __shared__ float sqb[16][KD];  // role B

    const int t = threadIdx.x;
    const int b = blockIdx.x;

    if (b < 128) {
        // ---- role A: scores = q_half @ keys^T  (64 keys x 32 rows) ----
        const int kt   = b & 7;          // 0..7
        const int rt   = (b >> 3) & 7;   // 0..7 (32 rows)
        const int side = b >> 6;         // 0..1
        const float* keys = side ? col_keys : row_keys;

        // stage keys transposed: sk[d][key]
        {
            const int d  = t & 63;
            const int k0 = t >> 6;       // 0..3
#pragma unroll
            for (int k = 0; k < 16; k++) {
                const int kl = k0 + k * 4;
                const int kg = kt * 64 + kl;
                sk[d][kl] = (kg < NK) ? keys[(size_t)kg * 64 + d] : 0.f;
            }
        }
        // stage q tile (32 rows x 64 half-dims)
#pragma unroll
        for (int k = 0; k < 8; k++) {
            const int idx = t + k * 256;
            const int r = idx >> 6, d = idx & 63;
            sq[r][d] = g_q[(size_t)(rt * 32 + r) * KD + side * 64 + d];
        }
        __syncthreads();

        const int kx = t & 31;           // key pair -> keys 2kx, 2kx+1
        const int rg = t >> 5;           // rows 4rg..4rg+3
        float a0x = 0.f, a0y = 0.f, a1x = 0.f, a1y = 0.f;
        float a2x = 0.f, a2y = 0.f, a3x = 0.f, a3y = 0.f;
#pragma unroll 8
        for (int d = 0; d < 64; d++) {
            const float2 kv = *(const float2*)&sk[d][2 * kx];
            const float q0 = sq[4 * rg + 0][d];
            const float q1 = sq[4 * rg + 1][d];
            const float q2 = sq[4 * rg + 2][d];
            const float q3 = sq[4 * rg + 3][d];
            a0x += q0 * kv.x; a0y += q0 * kv.y;
            a1x += q1 * kv.x; a1y += q1 * kv.y;
            a2x += q2 * kv.x; a2y += q2 * kv.y;
            a3x += q3 * kv.x; a3y += q3 * kv.y;
        }
        const int kg0 = kt * 64 + 2 * kx;
        if (kg0 < NK) {
            const int r0 = rt * 32 + 4 * rg;
            *(float2*)&g_sc[side][r0 + 0][kg0] = make_float2(a0x, a0y);
            *(float2*)&g_sc[side][r0 + 1][kg0] = make_float2(a1x, a1y);
            *(float2*)&g_sc[side][r0 + 2][kg0] = make_float2(a2x, a2y);
            *(float2*)&g_sc[side][r0 + 3][kg0] = make_float2(a3x, a3y);
        }
    } else {
        // ---- role B: query_projected = q @ Wqc + bqc (16 rows x 64 cols) ----
        const int b2 = b - 128;          // 0..191
        const int ct = b2 % 12;          // 64-col tile
        const int rt = b2 / 12;          // 16-row tile

#pragma unroll
        for (int k = 0; k < 8; k++) {
            const int idx = t + k * 256;
            const int r = idx >> 7, d = idx & 127;
            sqb[r][d] = g_q[(size_t)(rt * 16 + r) * KD + d];
        }
        __syncthreads();

        const int tx = t & 31;           // col pair
        const int ty = t >> 5;           // 8 row pairs
        const int col = ct * 64 + tx * 2;
        const int r0 = ty * 2;
        float a00 = 0.f, a01 = 0.f, a10 = 0.f, a11 = 0.f;
#pragma unroll 16
        for (int d = 0; d < KD; d++) {
            const float2 w = *(const float2*)&Wqc[(size_t)d * DDIM + col];
            const float q0 = sqb[r0 + 0][d];
            const float q1 = sqb[r0 + 1][d];
            a00 += q0 * w.x; a01 += q0 * w.y;
            a10 += q1 * w.x; a11 += q1 * w.y;
        }
        const float2 bb = *(const float2*)&bqc[col];
        const int grow = rt * 16 + r0;
        float* o = out + QP_OFF + (size_t)grow * DDIM + col;
        *(float2*)(o + 0 * DDIM) = make_float2(a00 + bb.x, a01 + bb.y);
        *(float2*)(o + 1 * DDIM) = make_float2(a10 + bb.x, a11 + bb.y);
    }
}

// ---------------------------------------------------------------------------
// KC: per-row top-4 per side, combine 4x4, write idx/scores, gather concepts
// ---------------------------------------------------------------------------
__global__ __launch_bounds__(128) void kc_topk_gather(
    const float* __restrict__ concepts,
    float* __restrict__ out)
{
    __shared__ float s_tv[2][TK];
    __shared__ int   s_ti[2][TK];
    __shared__ int   s_idx[TK];

    const int row  = blockIdx.x;
    const int t    = threadIdx.x;
    const int warp = t >> 5, lane = t & 31;

    if (warp < 2) {
        const float* sc = &g_sc[warp][row][0];
        float v[TK]; int id[TK];
#pragma unroll
        for (int j = 0; j < TK; j++) { v[j] = NEG_INF; id[j] = 0x7fffffff; }
        for (int i = lane; i < NK; i += 32) insert4(v, id, sc[i], i);
#pragma unroll
        for (int off = 16; off >= 1; off >>= 1) {
            float ov[TK]; int oi[TK];
#pragma unroll
            for (int j = 0; j < TK; j++) {
                ov[j] = __shfl_down_sync(0xffffffffu, v[j], off);
                oi[j] = __shfl_down_sync(0xffffffffu, id[j], off);
            }
            if (lane < off) {
#pragma unroll
                for (int j = 0; j < TK; j++) insert4(v, id, ov[j], oi[j]);
            }
        }
        if (lane == 0) {
#pragma unroll
            for (int j = 0; j < TK; j++) { s_tv[warp][j] = v[j]; s_ti[warp][j] = id[j]; }
        }
    }
    __syncthreads();

    if (t == 0) {
        float bv[TK]; int bi[TK];
#pragma unroll
        for (int j = 0; j < TK; j++) { bv[j] = NEG_INF; bi[j] = 0x7fffffff; }
#pragma unroll
        for (int i = 0; i < TK; i++)
#pragma unroll
            for (int j = 0; j < TK; j++)
                insert4(bv, bi, s_tv[0][i] + s_tv[1][j], s_ti[0][i] * NK + s_ti[1][j]);
#pragma unroll
        for (int n = 0; n < TK; n++) {
            out[SC_OFF  + row * TK + n] = bv[n];
            out[IDX_OFF + row * TK + n] = (float)bi[n];
            s_idx[n] = bi[n];
        }
    }
    __syncthreads();

    // gather 4 concept rows (4 x 192 float4), 6 per thread
#pragma unroll
    for (int k = 0; k < 6; k++) {
        const int i = t + k * 128;
        const int n = i / 192, j = i % 192;
        const int cid = s_idx[n];
        const float4 val = ((const float4*)concepts)[(size_t)cid * 192 + j];
        ((float4*)(out + OC_OFF))[(size_t)(row * TK + n) * 192 + j] = val;
    }
}

extern "C" void kernel_launch(void* const* d_in, const int* in_sizes, int n_in,
                              void* d_out, int out_size) {
    const float* regs     = (const float*)d_in[0];
    const float* row_keys = (const float*)d_in[1];
    const float* col_keys = (const float*)d_in[2];
    const float* concepts = (const float*)d_in[3];
    const float* gamma    = (const float*)d_in[4];
    const float* beta     = (const float*)d_in[5];
    const float* Wq       = (const float*)d_in[6];
    const float* bq       = (const float*)d_in[7];
    const float* Wqc      = (const float*)d_in[8];
    const float* bqc      = (const float*)d_in[9];
    float* out = (float*)d_out;

    k0_ln<<<256, 256>>>(regs, gamma, beta);
    k1_gemm<<<dim3(8, 32), 256>>>(Wq, bq);
    kb_scores_qp<<<320, 256>>>(row_keys, col_keys, Wqc, bqc, out);
    kc_topk_gather<<<256, 128>>>(concepts, out);
}

// round 8
// speedup vs baseline: 1.1159x; 1.1159x over previous
#include <cuda_runtime.h>
#include <cstdint>

#define NROWS 256
#define DDIM  768
#define KD    128
#define NK    500
#define TK    4

// output layout (float32, reference return order)
#define OC_OFF  0
#define IDX_OFF 786432
#define SC_OFF  787456
#define QP_OFF  788480

#define NEG_INF (-3.402823466e38f)

__device__ float g_xnT[DDIM * NROWS];      // normalized input, TRANSPOSED [d][row]
__device__ float g_q[NROWS * KD];          // queries
__device__ float g_sc[2][NROWS][NK];       // row/col scores

__device__ __forceinline__ bool better(float a, int ia, float b, int ib) {
    return (a > b) || (a == b && ia < ib);
}

__device__ __forceinline__ void insert4(float* v, int* id, float x, int ix) {
    if (!better(x, ix, v[3], id[3])) return;
    v[3] = x; id[3] = ix;
#pragma unroll
    for (int j = 3; j > 0; j--) {
        if (better(v[j], id[j], v[j - 1], id[j - 1])) {
            float tv = v[j]; v[j] = v[j - 1]; v[j - 1] = tv;
            int   ti = id[j]; id[j] = id[j - 1]; id[j - 1] = ti;
        }
    }
}

// ---------------------------------------------------------------------------
// K0: LayerNorm, one row per block; writes transposed normalized x
// ---------------------------------------------------------------------------
__global__ __launch_bounds__(256) void k0_ln(
    const float* __restrict__ regs,
    const float* __restrict__ gamma,
    const float* __restrict__ beta)
{
    __shared__ float red_s[8], red_q[8];
    __shared__ float s_mu, s_rs;

    const int row = blockIdx.x;
    const int t   = threadIdx.x;
    const int warp = t >> 5, lane = t & 31;

    const float x0 = regs[(size_t)row * DDIM + t];
    const float x1 = regs[(size_t)row * DDIM + t + 256];
    const float x2 = regs[(size_t)row * DDIM + t + 512];

    float s = x0 + x1 + x2;
    float q = x0 * x0 + x1 * x1 + x2 * x2;
#pragma unroll
    for (int o = 16; o; o >>= 1) {
        s += __shfl_xor_sync(0xffffffffu, s, o);
        q += __shfl_xor_sync(0xffffffffu, q, o);
    }
    if (lane == 0) { red_s[warp] = s; red_q[warp] = q; }
    __syncthreads();
    if (t < 32) {
        s = (t < 8) ? red_s[t] : 0.f;
        q = (t < 8) ? red_q[t] : 0.f;
#pragma unroll
        for (int o = 4; o; o >>= 1) {
            s += __shfl_xor_sync(0xffffffffu, s, o);
            q += __shfl_xor_sync(0xffffffffu, q, o);
        }
        if (t == 0) {
            const float mu  = s * (1.0f / DDIM);
            const float var = q * (1.0f / DDIM) - mu * mu;
            s_mu = mu;
            s_rs = rsqrtf(var + 1e-5f);
        }
    }
    __syncthreads();

    const float mu = s_mu, rs = s_rs;
    g_xnT[(size_t)(t      ) * NROWS + row] = (x0 - mu) * rs * gamma[t      ] + beta[t      ];
    g_xnT[(size_t)(t + 256) * NROWS + row] = (x1 - mu) * rs * gamma[t + 256] + beta[t + 256];
    g_xnT[(size_t)(t + 512) * NROWS + row] = (x2 - mu) * rs * gamma[t + 512] + beta[t + 512];
}

// ---------------------------------------------------------------------------
// K1: Q = xn @ Wq + bq, barrier-free mainloop
// grid (8 coltiles of 16, 32 rowtiles of 8), 256 threads
// ---------------------------------------------------------------------------
__global__ __launch_bounds__(256) void k1_gemm(
    const float* __restrict__ Wq,
    const float* __restrict__ bq)
{
    __shared__ __align__(16) float spart[8][8][16];  // [d8][row][col]

    const int t  = threadIdx.x;
    const int ct = blockIdx.x;     // 0..7  (16 cols)
    const int rt = blockIdx.y;     // 0..31 (8 rows)

    const int c4 = t & 3;
    const int s  = t >> 2;
    const int r  = s & 7;
    const int d8 = s >> 3;          // 0..7: 96-deep d slice

    const float* wp = Wq + (size_t)(d8 * 96) * KD + ct * 16 + c4 * 4;
    const float* xp = g_xnT + (size_t)(d8 * 96) * NROWS + rt * 8 + r;

    float ax = 0.f, ay = 0.f, az = 0.f, aw = 0.f;
#pragma unroll 8
    for (int d = 0; d < 96; d++) {
        const float4 w = *(const float4*)(wp + (size_t)d * KD);
        const float xv = xp[(size_t)d * NROWS];
        ax += xv * w.x; ay += xv * w.y; az += xv * w.z; aw += xv * w.w;
    }
    *(float4*)&spart[d8][r][c4 * 4] = make_float4(ax, ay, az, aw);
    __syncthreads();

    if (t < 128) {
        const int rr = t >> 4, c = t & 15;
        float sum = bq[ct * 16 + c];
#pragma unroll
        for (int k = 0; k < 8; k++) sum += spart[k][rr][c];
        g_q[(size_t)(rt * 8 + rr) * KD + ct * 16 + c] = sum;
    }
}

// ---------------------------------------------------------------------------
// KB: merged scores (blocks 0..127) + query_projected (blocks 128..319)
// ---------------------------------------------------------------------------
__global__ __launch_bounds__(256) void kb_scores_qp(
    const float* __restrict__ row_keys,
    const float* __restrict__ col_keys,
    const float* __restrict__ Wqc,
    const float* __restrict__ bqc,
    float* __restrict__ out)
{
    __shared__ float sk[64][66];   // role A: keys, d-major (transposed)
    __shared__ float sq[32][64];   // role A: q halves
    __shared__ float sqb[16][KD];  // role B

    const int t = threadIdx.x;
    const int b = blockIdx.x;

    if (b < 128) {
        // ---- role A: scores = q_half @ keys^T  (64 keys x 32 rows) ----
        const int kt   = b & 7;          // 0..7
        const int rt   = (b >> 3) & 7;   // 0..7 (32 rows)
        const int side = b >> 6;         // 0..1
        const float* keys = side ? col_keys : row_keys;

        // stage keys transposed: sk[d][key]
        {
            const int d  = t & 63;
            const int k0 = t >> 6;       // 0..3
#pragma unroll
            for (int k = 0; k < 16; k++) {
                const int kl = k0 + k * 4;
                const int kg = kt * 64 + kl;
                sk[d][kl] = (kg < NK) ? keys[(size_t)kg * 64 + d] : 0.f;
            }
        }
        // stage q tile (32 rows x 64 half-dims)
#pragma unroll
        for (int k = 0; k < 8; k++) {
            const int idx = t + k * 256;
            const int r = idx >> 6, d = idx & 63;
            sq[r][d] = g_q[(size_t)(rt * 32 + r) * KD + side * 64 + d];
        }
        __syncthreads();

        const int kx = t & 31;           // key pair -> keys 2kx, 2kx+1
        const int rg = t >> 5;           // rows 4rg..4rg+3
        float a0x = 0.f, a0y = 0.f, a1x = 0.f, a1y = 0.f;
        float a2x = 0.f, a2y = 0.f, a3x = 0.f, a3y = 0.f;
#pragma unroll 8
        for (int d = 0; d < 64; d++) {
            const float2 kv = *(const float2*)&sk[d][2 * kx];
            const float q0 = sq[4 * rg + 0][d];
            const float q1 = sq[4 * rg + 1][d];
            const float q2 = sq[4 * rg + 2][d];
            const float q3 = sq[4 * rg + 3][d];
            a0x += q0 * kv.x; a0y += q0 * kv.y;
            a1x += q1 * kv.x; a1y += q1 * kv.y;
            a2x += q2 * kv.x; a2y += q2 * kv.y;
            a3x += q3 * kv.x; a3y += q3 * kv.y;
        }
        const int kg0 = kt * 64 + 2 * kx;
        if (kg0 < NK) {
            const int r0 = rt * 32 + 4 * rg;
            *(float2*)&g_sc[side][r0 + 0][kg0] = make_float2(a0x, a0y);
            *(float2*)&g_sc[side][r0 + 1][kg0] = make_float2(a1x, a1y);
            *(float2*)&g_sc[side][r0 + 2][kg0] = make_float2(a2x, a2y);
            *(float2*)&g_sc[side][r0 + 3][kg0] = make_float2(a3x, a3y);
        }
    } else {
        // ---- role B: query_projected = q @ Wqc + bqc (16 rows x 64 cols) ----
        const int b2 = b - 128;          // 0..191
        const int ct = b2 % 12;          // 64-col tile
        const int rt = b2 / 12;          // 16-row tile

#pragma unroll
        for (int k = 0; k < 8; k++) {
            const int idx = t + k * 256;
            const int r = idx >> 7, d = idx & 127;
            sqb[r][d] = g_q[(size_t)(rt * 16 + r) * KD + d];
        }
        __syncthreads();

        const int tx = t & 31;           // col pair
        const int ty = t >> 5;           // 8 row pairs
        const int col = ct * 64 + tx * 2;
        const int r0 = ty * 2;
        float a00 = 0.f, a01 = 0.f, a10 = 0.f, a11 = 0.f;
#pragma unroll 16
        for (int d = 0; d < KD; d++) {
            const float2 w = *(const float2*)&Wqc[(size_t)d * DDIM + col];
            const float q0 = sqb[r0 + 0][d];
            const float q1 = sqb[r0 + 1][d];
            a00 += q0 * w.x; a01 += q0 * w.y;
            a10 += q1 * w.x; a11 += q1 * w.y;
        }
        const float2 bb = *(const float2*)&bqc[col];
        const int grow = rt * 16 + r0;
        float* o = out + QP_OFF + (size_t)grow * DDIM + col;
        *(float2*)(o + 0 * DDIM) = make_float2(a00 + bb.x, a01 + bb.y);
        *(float2*)(o + 1 * DDIM) = make_float2(a10 + bb.x, a11 + bb.y);
    }
}

// ---------------------------------------------------------------------------
// KC: per-row top-4 per side (4 warps, prefetched), combine, gather
// grid 256 (one row), 256 threads
// ---------------------------------------------------------------------------
__global__ __launch_bounds__(256) void kc_topk_gather(
    const float* __restrict__ concepts,
    float* __restrict__ out)
{
    __shared__ float s_tv[2][2][TK];   // [side][half]
    __shared__ int   s_ti[2][2][TK];
    __shared__ int   s_idx[TK];

    const int row  = blockIdx.x;
    const int t    = threadIdx.x;
    const int warp = t >> 5, lane = t & 31;

    if (warp < 4) {
        const int side = warp >> 1;
        const int half = warp & 1;
        const float* sc = &g_sc[side][row][0];

        // prefetch 8 elements (indices half*32 + lane + 64k cover [0,512))
        float val[8];
        int   idx[8];
#pragma unroll
        for (int k = 0; k < 8; k++) {
            const int i = half * 32 + lane + 64 * k;
            idx[k] = i;
            val[k] = (i < NK) ? sc[i] : NEG_INF;
        }

        float v[TK]; int id[TK];
#pragma unroll
        for (int j = 0; j < TK; j++) { v[j] = NEG_INF; id[j] = 0x7fffffff; }
#pragma unroll
        for (int k = 0; k < 8; k++) insert4(v, id, val[k], idx[k]);

        // warp reduce to lane 0
#pragma unroll
        for (int off = 16; off >= 1; off >>= 1) {
            float ov[TK]; int oi[TK];
#pragma unroll
            for (int j = 0; j < TK; j++) {
                ov[j] = __shfl_down_sync(0xffffffffu, v[j], off);
                oi[j] = __shfl_down_sync(0xffffffffu, id[j], off);
            }
            if (lane < off) {
#pragma unroll
                for (int j = 0; j < TK; j++) insert4(v, id, ov[j], oi[j]);
            }
        }
        if (lane == 0) {
#pragma unroll
            for (int j = 0; j < TK; j++) { s_tv[side][half][j] = v[j]; s_ti[side][half][j] = id[j]; }
        }
    }
    __syncthreads();

    if (t == 0) {
        // merge halves per side
        float fv[2][TK]; int fi[2][TK];
#pragma unroll
        for (int sd = 0; sd < 2; sd++) {
#pragma unroll
            for (int j = 0; j < TK; j++) { fv[sd][j] = NEG_INF; fi[sd][j] = 0x7fffffff; }
#pragma unroll
            for (int h = 0; h < 2; h++)
#pragma unroll
                for (int j = 0; j < TK; j++)
                    insert4(fv[sd], fi[sd], s_tv[sd][h][j], s_ti[sd][h][j]);
        }
        // 4x4 combine (value desc, flat idx asc)
        float bv[TK]; int bi[TK];
#pragma unroll
        for (int j = 0; j < TK; j++) { bv[j] = NEG_INF; bi[j] = 0x7fffffff; }
#pragma unroll
        for (int i = 0; i < TK; i++)
#pragma unroll
            for (int j = 0; j < TK; j++)
                insert4(bv, bi, fv[0][i] + fv[1][j], fi[0][i] * NK + fi[1][j]);
#pragma unroll
        for (int n = 0; n < TK; n++) {
            out[SC_OFF  + row * TK + n] = bv[n];
            out[IDX_OFF + row * TK + n] = (float)bi[n];
            s_idx[n] = bi[n];
        }
    }
    __syncthreads();

    // gather 4 concept rows (4 x 192 float4), 3 per thread
#pragma unroll
    for (int k = 0; k < 3; k++) {
        const int i = t + k * 256;
        const int n = i / 192, j = i % 192;
        const int cid = s_idx[n];
        const float4 val = ((const float4*)concepts)[(size_t)cid * 192 + j];
        ((float4*)(out + OC_OFF))[(size_t)(row * TK + n) * 192 + j] = val;
    }
}

extern "C" void kernel_launch(void* const* d_in, const int* in_sizes, int n_in,
                              void* d_out, int out_size) {
    const float* regs     = (const float*)d_in[0];
    const float* row_keys = (const float*)d_in[1];
    const float* col_keys = (const float*)d_in[2];
    const float* concepts = (const float*)d_in[3];
    const float* gamma    = (const float*)d_in[4];
    const float* beta     = (const float*)d_in[5];
    const float* Wq       = (const float*)d_in[6];
    const float* bq       = (const float*)d_in[7];
    const float* Wqc      = (const float*)d_in[8];
    const float* bqc      = (const float*)d_in[9];
    float* out = (float*)d_out;

    k0_ln<<<256, 256>>>(regs, gamma, beta);
    k1_gemm<<<dim3(8, 32), 256>>>(Wq, bq);
    kb_scores_qp<<<320, 256>>>(row_keys, col_keys, Wqc, bqc, out);
    kc_topk_gather<<<256, 256>>>(concepts, out);
}

// round 9
// speedup vs baseline: 1.5734x; 1.4100x over previous
#include <cuda_runtime.h>
#include <cstdint>

#define NROWS 256
#define DDIM  768
#define KD    128
#define NK    500
#define TK    4

// output layout (float32, reference return order)
#define OC_OFF  0
#define IDX_OFF 786432
#define SC_OFF  787456
#define QP_OFF  788480

#define NEG_INF (-3.402823466e38f)

__device__ float g_q[NROWS * KD];                      // queries
__device__ unsigned long long g_cand[2][NROWS][32];    // per (side,row): 8 tiles x top-4, packed

// ---- packed candidate: sortable float in high 32, ~idx in low 32 ----
__device__ __forceinline__ unsigned long long packcand(float f, int idx) {
    unsigned int b = __float_as_uint(f);
    unsigned int s = (b & 0x80000000u) ? ~b : (b | 0x80000000u);
    return ((unsigned long long)s << 32) | (unsigned int)(~idx);
}
__device__ __forceinline__ float unpackval(unsigned long long c) {
    unsigned int s = (unsigned int)(c >> 32);
    unsigned int b = (s & 0x80000000u) ? (s & 0x7FFFFFFFu) : ~s;
    return __uint_as_float(b);
}
__device__ __forceinline__ int unpackidx(unsigned long long c) {
    return (int)(~(unsigned int)(c & 0xFFFFFFFFu));
}

// sorted desc top-4 list of packed u64
__device__ __forceinline__ void insert4u(unsigned long long* v, unsigned long long x) {
    if (x <= v[3]) return;
    v[3] = x;
    if (v[3] > v[2]) { unsigned long long tt = v[3]; v[3] = v[2]; v[2] = tt; }
    if (v[2] > v[1]) { unsigned long long tt = v[2]; v[2] = v[1]; v[1] = tt; }
    if (v[1] > v[0]) { unsigned long long tt = v[1]; v[1] = v[0]; v[0] = tt; }
}

// ---------------------------------------------------------------------------
// K1: LN + Q = LN(x) @ Wq + bq   (merged, R6 layout)
// grid (8 coltiles of 16, 32 rowtiles of 8), 256 threads
// ---------------------------------------------------------------------------
__global__ __launch_bounds__(256) void k1_ln_q(
    const float* __restrict__ regs,
    const float* __restrict__ gamma,
    const float* __restrict__ beta,
    const float* __restrict__ Wq,
    const float* __restrict__ bq)
{
    __shared__ __align__(16) float sx[8][772];       // padded
    __shared__ __align__(16) float spart[8][8][16];  // [d8][row][col]
    __shared__ float s_mu[8], s_rs[8];

    const int t  = threadIdx.x;
    const int ct = blockIdx.x;     // 0..7  (16 cols)
    const int rt = blockIdx.y;     // 0..31 (8 rows)
    const int warp = t >> 5, lane = t & 31;

    // stage 8 input rows
    {
        const float4* src = (const float4*)(regs + (size_t)rt * 8 * DDIM);
#pragma unroll
        for (int k = 0; k < 6; k++) {
            const int idx = t + k * 256;            // 0..1535
            const int r = idx / 192, j = idx % 192;
            *(float4*)&sx[r][j * 4] = src[idx];
        }
    }
    __syncthreads();

    // LN stats: warp w handles row w
    {
        float s = 0.f;
        for (int i = lane; i < DDIM; i += 32) s += sx[warp][i];
#pragma unroll
        for (int o = 16; o; o >>= 1) s += __shfl_xor_sync(0xffffffffu, s, o);
        const float mu = s * (1.0f / DDIM);
        float q = 0.f;
        for (int i = lane; i < DDIM; i += 32) { float d = sx[warp][i] - mu; q += d * d; }
#pragma unroll
        for (int o = 16; o; o >>= 1) q += __shfl_xor_sync(0xffffffffu, q, o);
        if (lane == 0) {
            s_mu[warp] = mu;
            s_rs[warp] = rsqrtf(q * (1.0f / DDIM) + 1e-5f);
        }
    }
    __syncthreads();

    // normalize in place
    {
        const float g0 = gamma[t], g1 = gamma[t + 256], g2 = gamma[t + 512];
        const float b0 = beta[t],  b1 = beta[t + 256],  b2 = beta[t + 512];
#pragma unroll
        for (int r = 0; r < 8; r++) {
            const float mu = s_mu[r], rs = s_rs[r];
            sx[r][t      ] = (sx[r][t      ] - mu) * rs * g0 + b0;
            sx[r][t + 256] = (sx[r][t + 256] - mu) * rs * g1 + b1;
            sx[r][t + 512] = (sx[r][t + 512] - mu) * rs * g2 + b2;
        }
    }
    __syncthreads();

    // GEMM: c4 = col quad, s -> (row, d-slice of 96)
    {
        const int c4 = t & 3;
        const int s  = t >> 2;
        const int r  = s & 7;
        const int d8 = s >> 3;
        const float* wp = Wq + (size_t)(d8 * 96) * KD + ct * 16 + c4 * 4;
        const float* xp = &sx[r][d8 * 96];
        float ax = 0.f, ay = 0.f, az = 0.f, aw = 0.f;
#pragma unroll 8
        for (int d = 0; d < 96; d++) {
            const float4 w = *(const float4*)(wp + (size_t)d * KD);
            const float xv = xp[d];
            ax += xv * w.x; ay += xv * w.y; az += xv * w.z; aw += xv * w.w;
        }
        *(float4*)&spart[d8][r][c4 * 4] = make_float4(ax, ay, az, aw);
    }
    __syncthreads();

    if (t < 128) {
        const int r = t >> 4, c = t & 15;
        float sum = bq[ct * 16 + c];
#pragma unroll
        for (int k = 0; k < 8; k++) sum += spart[k][r][c];
        g_q[(size_t)(rt * 8 + r) * KD + ct * 16 + c] = sum;
    }
}

// ---------------------------------------------------------------------------
// KB: merged scores+candidate-topk (blocks 0..127) + query_projected (128..319)
// ---------------------------------------------------------------------------
__global__ __launch_bounds__(256) void kb_scores_qp(
    const float* __restrict__ row_keys,
    const float* __restrict__ col_keys,
    const float* __restrict__ Wqc,
    const float* __restrict__ bqc,
    float* __restrict__ out)
{
    __shared__ float sk[64][66];   // role A: keys, d-major
    __shared__ float sq[32][64];   // role A: q halves
    __shared__ float ss[32][66];   // role A: scores (rows x keys), padded
    __shared__ float sqb[16][KD];  // role B

    const int t = threadIdx.x;
    const int b = blockIdx.x;
    const int warp = t >> 5, lane = t & 31;

    if (b < 128) {
        // ---- role A: scores = q_half @ keys^T  (64 keys x 32 rows) ----
        const int kt   = b & 7;          // 0..7
        const int rt   = (b >> 3) & 7;   // 0..7 (32 rows)
        const int side = b >> 6;         // 0..1
        const float* keys = side ? col_keys : row_keys;

        // stage keys transposed: sk[d][key]
        {
            const int d  = t & 63;
            const int k0 = t >> 6;       // 0..3
#pragma unroll
            for (int k = 0; k < 16; k++) {
                const int kl = k0 + k * 4;
                const int kg = kt * 64 + kl;
                sk[d][kl] = (kg < NK) ? keys[(size_t)kg * 64 + d] : 0.f;
            }
        }
        // stage q tile (32 rows x 64 half-dims)
#pragma unroll
        for (int k = 0; k < 8; k++) {
            const int idx = t + k * 256;
            const int r = idx >> 6, d = idx & 63;
            sq[r][d] = g_q[(size_t)(rt * 32 + r) * KD + side * 64 + d];
        }
        __syncthreads();

        const int kx = t & 31;           // key pair -> keys 2kx, 2kx+1
        const int rg = warp;             // rows 4rg..4rg+3
        float a0x = 0.f, a0y = 0.f, a1x = 0.f, a1y = 0.f;
        float a2x = 0.f, a2y = 0.f, a3x = 0.f, a3y = 0.f;
#pragma unroll 8
        for (int d = 0; d < 64; d++) {
            const float2 kv = *(const float2*)&sk[d][2 * kx];
            const float q0 = sq[4 * rg + 0][d];
            const float q1 = sq[4 * rg + 1][d];
            const float q2 = sq[4 * rg + 2][d];
            const float q3 = sq[4 * rg + 3][d];
            a0x += q0 * kv.x; a0y += q0 * kv.y;
            a1x += q1 * kv.x; a1y += q1 * kv.y;
            a2x += q2 * kv.x; a2y += q2 * kv.y;
            a3x += q3 * kv.x; a3y += q3 * kv.y;
        }
        // park scores in smem (transpose to row-per-lane-group layout)
        *(float2*)&ss[4 * rg + 0][2 * kx] = make_float2(a0x, a0y);
        *(float2*)&ss[4 * rg + 1][2 * kx] = make_float2(a1x, a1y);
        *(float2*)&ss[4 * rg + 2][2 * kx] = make_float2(a2x, a2y);
        *(float2*)&ss[4 * rg + 3][2 * kx] = make_float2(a3x, a3y);
        __syncthreads();

        // per-row top-4 extraction: warp w -> rows 4w..4w+3 (8 lanes per row)
        {
            const int rl    = lane >> 3;         // row within warp's group
            const int kslot = lane & 7;          // 8 keys per lane
            const int row_l = 4 * warp + rl;     // local row 0..31
            unsigned long long v[4] = {0ull, 0ull, 0ull, 0ull};
            const float* sp = &ss[row_l][kslot * 8];
#pragma unroll
            for (int j = 0; j < 8; j++) {
                const int kg = kt * 64 + kslot * 8 + j;
                if (kg < NK) insert4u(v, packcand(sp[j], kg));
            }
            // merge sorted-4 lists across the 8 lanes of this row group
#pragma unroll
            for (int off = 4; off >= 1; off >>= 1) {
                unsigned long long o[4];
#pragma unroll
                for (int j = 0; j < 4; j++)
                    o[j] = __shfl_down_sync(0xffffffffu, v[j], off, 8);
                if (kslot < off) {
#pragma unroll
                    for (int j = 0; j < 4; j++) insert4u(v, o[j]);
                }
            }
            if (kslot == 0) {
                const int row_g = rt * 32 + row_l;
#pragma unroll
                for (int n = 0; n < 4; n++)
                    g_cand[side][row_g][kt * 4 + n] = v[n];
            }
        }
    } else {
        // ---- role B: query_projected = q @ Wqc + bqc (16 rows x 64 cols) ----
        const int b2 = b - 128;          // 0..191
        const int ct = b2 % 12;          // 64-col tile
        const int rt = b2 / 12;          // 16-row tile

#pragma unroll
        for (int k = 0; k < 8; k++) {
            const int idx = t + k * 256;
            const int r = idx >> 7, d = idx & 127;
            sqb[r][d] = g_q[(size_t)(rt * 16 + r) * KD + d];
        }
        __syncthreads();

        const int tx = t & 31;           // col pair
        const int ty = t >> 5;           // 8 row pairs
        const int col = ct * 64 + tx * 2;
        const int r0 = ty * 2;
        float a00 = 0.f, a01 = 0.f, a10 = 0.f, a11 = 0.f;
#pragma unroll 16
        for (int d = 0; d < KD; d++) {
            const float2 w = *(const float2*)&Wqc[(size_t)d * DDIM + col];
            const float q0 = sqb[r0 + 0][d];
            const float q1 = sqb[r0 + 1][d];
            a00 += q0 * w.x; a01 += q0 * w.y;
            a10 += q1 * w.x; a11 += q1 * w.y;
        }
        const float2 bb = *(const float2*)&bqc[col];
        const int grow = rt * 16 + r0;
        float* o = out + QP_OFF + (size_t)grow * DDIM + col;
        *(float2*)(o + 0 * DDIM) = make_float2(a00 + bb.x, a01 + bb.y);
        *(float2*)(o + 1 * DDIM) = make_float2(a10 + bb.x, a11 + bb.y);
    }
}

// ---------------------------------------------------------------------------
// KC: reduce 32 candidates per side, combine 4x4, write, gather
// grid 256 (one row), 256 threads
// ---------------------------------------------------------------------------
__global__ __launch_bounds__(256) void kc_topk_gather(
    const float* __restrict__ concepts,
    float* __restrict__ out)
{
    __shared__ unsigned long long s_top[2][TK];
    __shared__ int s_idx[TK];

    const int row  = blockIdx.x;
    const int t    = threadIdx.x;
    const int warp = t >> 5, lane = t & 31;

    // warps 0/1: per-side top-4 by 4-round u64 max extraction over 32 candidates
    if (warp < 2) {
        const int side = warp;
        unsigned long long c = g_cand[side][row][lane];
#pragma unroll
        for (int n = 0; n < TK; n++) {
            unsigned long long m = c;
#pragma unroll
            for (int off = 16; off >= 1; off >>= 1) {
                unsigned long long o = __shfl_xor_sync(0xffffffffu, m, off);
                if (o > m) m = o;
            }
            if (lane == 0) s_top[side][n] = m;
            if (c == m) c = 0ull;
        }
    }
    __syncthreads();

    // warp 2: 4x4 combine on 16 lanes, 4-round extraction
    if (warp == 2) {
        unsigned long long c = 0ull;
        if (lane < 16) {
            const unsigned long long r4 = s_top[0][lane >> 2];
            const unsigned long long c4 = s_top[1][lane & 3];
            const float sum = unpackval(r4) + unpackval(c4);
            const int flat  = unpackidx(r4) * NK + unpackidx(c4);
            c = packcand(sum, flat);
        }
#pragma unroll
        for (int n = 0; n < TK; n++) {
            unsigned long long m = c;
#pragma unroll
            for (int off = 16; off >= 1; off >>= 1) {
                unsigned long long o = __shfl_xor_sync(0xffffffffu, m, off);
                if (o > m) m = o;
            }
            if (lane == 0) {
                out[SC_OFF  + row * TK + n] = unpackval(m);
                const int fi = unpackidx(m);
                out[IDX_OFF + row * TK + n] = (float)fi;
                s_idx[n] = fi;
            }
            if (c == m) c = 0ull;
        }
    }
    __syncthreads();

    // gather 4 concept rows (4 x 192 float4), 3 per thread
#pragma unroll
    for (int k = 0; k < 3; k++) {
        const int i = t + k * 256;
        const int n = i / 192, j = i % 192;
        const int cid = s_idx[n];
        const float4 val = ((const float4*)concepts)[(size_t)cid * 192 + j];
        ((float4*)(out + OC_OFF))[(size_t)(row * TK + n) * 192 + j] = val;
    }
}

extern "C" void kernel_launch(void* const* d_in, const int* in_sizes, int n_in,
                              void* d_out, int out_size) {
    const float* regs     = (const float*)d_in[0];
    const float* row_keys = (const float*)d_in[1];
    const float* col_keys = (const float*)d_in[2];
    const float* concepts = (const float*)d_in[3];
    const float* gamma    = (const float*)d_in[4];
    const float* beta     = (const float*)d_in[5];
    const float* Wq       = (const float*)d_in[6];
    const float* bq       = (const float*)d_in[7];
    const float* Wqc      = (const float*)d_in[8];
    const float* bqc      = (const float*)d_in[9];
    float* out = (float*)d_out;

    k1_ln_q<<<dim3(8, 32), 256>>>(regs, gamma, beta, Wq, bq);
    kb_scores_qp<<<320, 256>>>(row_keys, col_keys, Wqc, bqc, out);
    kc_topk_gather<<<256, 256>>>(concepts, out);
}

// round 10
// speedup vs baseline: 1.6946x; 1.0770x over previous
#include <cuda_runtime.h>
#include <cstdint>

#define NROWS 256
#define DDIM  768
#define KD    128
#define NK    500
#define TK    4

// output layout (float32, reference return order)
#define OC_OFF  0
#define IDX_OFF 786432
#define SC_OFF  787456
#define QP_OFF  788480

#define NEG_INF (-3.402823466e38f)

__device__ float g_q[NROWS * KD];                      // queries
__device__ unsigned long long g_cand[2][NROWS][32];    // per (side,row): 8 tiles x top-4, packed

// ---- packed candidate: sortable float in high 32, ~idx in low 32 ----
__device__ __forceinline__ unsigned long long packcand(float f, int idx) {
    unsigned int b = __float_as_uint(f);
    unsigned int s = (b & 0x80000000u) ? ~b : (b | 0x80000000u);
    return ((unsigned long long)s << 32) | (unsigned int)(~idx);
}
__device__ __forceinline__ float unpackval(unsigned long long c) {
    unsigned int s = (unsigned int)(c >> 32);
    unsigned int b = (s & 0x80000000u) ? (s & 0x7FFFFFFFu) : ~s;
    return __uint_as_float(b);
}
__device__ __forceinline__ int unpackidx(unsigned long long c) {
    return (int)(~(unsigned int)(c & 0xFFFFFFFFu));
}

// sorted desc top-4 list of packed u64
__device__ __forceinline__ void insert4u(unsigned long long* v, unsigned long long x) {
    if (x <= v[3]) return;
    v[3] = x;
    if (v[3] > v[2]) { unsigned long long tt = v[3]; v[3] = v[2]; v[2] = tt; }
    if (v[2] > v[1]) { unsigned long long tt = v[2]; v[2] = v[1]; v[1] = tt; }
    if (v[1] > v[0]) { unsigned long long tt = v[1]; v[1] = v[0]; v[0] = tt; }
}

// ---------------------------------------------------------------------------
// K1: LN + Q = LN(x) @ Wq + bq
// grid (8 coltiles of 16, 32 rowtiles of 8), 256 threads
// GEMM inner loop explicitly batched: 12 groups x 8 independent LDG.128
// ---------------------------------------------------------------------------
__global__ __launch_bounds__(256) void k1_ln_q(
    const float* __restrict__ regs,
    const float* __restrict__ gamma,
    const float* __restrict__ beta,
    const float* __restrict__ Wq,
    const float* __restrict__ bq)
{
    __shared__ __align__(16) float sx[8][772];       // padded
    __shared__ __align__(16) float spart[8][8][16];  // [d8][row][col]
    __shared__ float s_mu[8], s_rs[8];

    const int t  = threadIdx.x;
    const int ct = blockIdx.x;     // 0..7  (16 cols)
    const int rt = blockIdx.y;     // 0..31 (8 rows)
    const int warp = t >> 5, lane = t & 31;

    // stage 8 input rows
    {
        const float4* src = (const float4*)(regs + (size_t)rt * 8 * DDIM);
#pragma unroll
        for (int k = 0; k < 6; k++) {
            const int idx = t + k * 256;            // 0..1535
            const int r = idx / 192, j = idx % 192;
            *(float4*)&sx[r][j * 4] = src[idx];
        }
    }
    __syncthreads();

    // LN stats: warp w handles row w, ONE pass (sum + sumsq)
    {
        float s = 0.f, q = 0.f;
        for (int i = lane; i < DDIM; i += 32) {
            const float xv = sx[warp][i];
            s += xv;
            q += xv * xv;
        }
#pragma unroll
        for (int o = 16; o; o >>= 1) {
            s += __shfl_xor_sync(0xffffffffu, s, o);
            q += __shfl_xor_sync(0xffffffffu, q, o);
        }
        if (lane == 0) {
            const float mu  = s * (1.0f / DDIM);
            const float var = q * (1.0f / DDIM) - mu * mu;
            s_mu[warp] = mu;
            s_rs[warp] = rsqrtf(var + 1e-5f);
        }
    }
    __syncthreads();

    // normalize in place
    {
        const float g0 = gamma[t], g1 = gamma[t + 256], g2 = gamma[t + 512];
        const float b0 = beta[t],  b1 = beta[t + 256],  b2 = beta[t + 512];
#pragma unroll
        for (int r = 0; r < 8; r++) {
            const float mu = s_mu[r], rs = s_rs[r];
            sx[r][t      ] = (sx[r][t      ] - mu) * rs * g0 + b0;
            sx[r][t + 256] = (sx[r][t + 256] - mu) * rs * g1 + b1;
            sx[r][t + 512] = (sx[r][t + 512] - mu) * rs * g2 + b2;
        }
    }
    __syncthreads();

    // GEMM: c4 = col quad, s -> (row, d-slice of 96)
    {
        const int c4 = t & 3;
        const int s  = t >> 2;
        const int r  = s & 7;
        const int d8 = s >> 3;
        const float* wp = Wq + (size_t)(d8 * 96) * KD + ct * 16 + c4 * 4;
        const float4* xp4 = (const float4*)&sx[r][d8 * 96];

        float ax = 0.f, ay = 0.f, az = 0.f, aw = 0.f;
#pragma unroll 1
        for (int g = 0; g < 12; g++) {
            // 8 independent global loads (MLP 8)
            float4 w0 = *(const float4*)(wp + (size_t)(g * 8 + 0) * KD);
            float4 w1 = *(const float4*)(wp + (size_t)(g * 8 + 1) * KD);
            float4 w2 = *(const float4*)(wp + (size_t)(g * 8 + 2) * KD);
            float4 w3 = *(const float4*)(wp + (size_t)(g * 8 + 3) * KD);
            float4 w4 = *(const float4*)(wp + (size_t)(g * 8 + 4) * KD);
            float4 w5 = *(const float4*)(wp + (size_t)(g * 8 + 5) * KD);
            float4 w6 = *(const float4*)(wp + (size_t)(g * 8 + 6) * KD);
            float4 w7 = *(const float4*)(wp + (size_t)(g * 8 + 7) * KD);
            const float4 xa = xp4[g * 2 + 0];
            const float4 xb = xp4[g * 2 + 1];

            ax += xa.x * w0.x; ay += xa.x * w0.y; az += xa.x * w0.z; aw += xa.x * w0.w;
            ax += xa.y * w1.x; ay += xa.y * w1.y; az += xa.y * w1.z; aw += xa.y * w1.w;
            ax += xa.z * w2.x; ay += xa.z * w2.y; az += xa.z * w2.z; aw += xa.z * w2.w;
            ax += xa.w * w3.x; ay += xa.w * w3.y; az += xa.w * w3.z; aw += xa.w * w3.w;
            ax += xb.x * w4.x; ay += xb.x * w4.y; az += xb.x * w4.z; aw += xb.x * w4.w;
            ax += xb.y * w5.x; ay += xb.y * w5.y; az += xb.y * w5.z; aw += xb.y * w5.w;
            ax += xb.z * w6.x; ay += xb.z * w6.y; az += xb.z * w6.z; aw += xb.z * w6.w;
            ax += xb.w * w7.x; ay += xb.w * w7.y; az += xb.w * w7.z; aw += xb.w * w7.w;
        }
        *(float4*)&spart[d8][r][c4 * 4] = make_float4(ax, ay, az, aw);
    }
    __syncthreads();

    if (t < 128) {
        const int r = t >> 4, c = t & 15;
        float sum = bq[ct * 16 + c];
#pragma unroll
        for (int k = 0; k < 8; k++) sum += spart[k][r][c];
        g_q[(size_t)(rt * 8 + r) * KD + ct * 16 + c] = sum;
    }
}

// ---------------------------------------------------------------------------
// KB: merged scores+candidate-topk (blocks 0..127) + query_projected (128..319)
// ---------------------------------------------------------------------------
__global__ __launch_bounds__(256) void kb_scores_qp(
    const float* __restrict__ row_keys,
    const float* __restrict__ col_keys,
    const float* __restrict__ Wqc,
    const float* __restrict__ bqc,
    float* __restrict__ out)
{
    __shared__ float sk[64][66];   // role A: keys, d-major
    __shared__ float sq[32][64];   // role A: q halves
    __shared__ float ss[32][66];   // role A: scores (rows x keys), padded
    __shared__ float sqb[16][KD];  // role B

    const int t = threadIdx.x;
    const int b = blockIdx.x;
    const int warp = t >> 5, lane = t & 31;

    if (b < 128) {
        // ---- role A: scores = q_half @ keys^T  (64 keys x 32 rows) ----
        const int kt   = b & 7;          // 0..7
        const int rt   = (b >> 3) & 7;   // 0..7 (32 rows)
        const int side = b >> 6;         // 0..1
        const float* keys = side ? col_keys : row_keys;

        // stage keys transposed: sk[d][key]
        {
            const int d  = t & 63;
            const int k0 = t >> 6;       // 0..3
#pragma unroll
            for (int k = 0; k < 16; k++) {
                const int kl = k0 + k * 4;
                const int kg = kt * 64 + kl;
                sk[d][kl] = (kg < NK) ? keys[(size_t)kg * 64 + d] : 0.f;
            }
        }
        // stage q tile (32 rows x 64 half-dims)
#pragma unroll
        for (int k = 0; k < 8; k++) {
            const int idx = t + k * 256;
            const int r = idx >> 6, d = idx & 63;
            sq[r][d] = g_q[(size_t)(rt * 32 + r) * KD + side * 64 + d];
        }
        __syncthreads();

        const int kx = t & 31;           // key pair -> keys 2kx, 2kx+1
        const int rg = warp;             // rows 4rg..4rg+3
        float a0x = 0.f, a0y = 0.f, a1x = 0.f, a1y = 0.f;
        float a2x = 0.f, a2y = 0.f, a3x = 0.f, a3y = 0.f;
#pragma unroll 8
        for (int d = 0; d < 64; d++) {
            const float2 kv = *(const float2*)&sk[d][2 * kx];
            const float q0 = sq[4 * rg + 0][d];
            const float q1 = sq[4 * rg + 1][d];
            const float q2 = sq[4 * rg + 2][d];
            const float q3 = sq[4 * rg + 3][d];
            a0x += q0 * kv.x; a0y += q0 * kv.y;
            a1x += q1 * kv.x; a1y += q1 * kv.y;
            a2x += q2 * kv.x; a2y += q2 * kv.y;
            a3x += q3 * kv.x; a3y += q3 * kv.y;
        }
        // park scores in smem
        *(float2*)&ss[4 * rg + 0][2 * kx] = make_float2(a0x, a0y);
        *(float2*)&ss[4 * rg + 1][2 * kx] = make_float2(a1x, a1y);
        *(float2*)&ss[4 * rg + 2][2 * kx] = make_float2(a2x, a2y);
        *(float2*)&ss[4 * rg + 3][2 * kx] = make_float2(a3x, a3y);
        __syncthreads();

        // per-row top-4 extraction: warp w -> rows 4w..4w+3 (8 lanes per row)
        {
            const int rl    = lane >> 3;         // row within warp's group
            const int kslot = lane & 7;          // 8 keys per lane
            const int row_l = 4 * warp + rl;     // local row 0..31
            unsigned long long v[4] = {0ull, 0ull, 0ull, 0ull};
            const float* sp = &ss[row_l][kslot * 8];
#pragma unroll
            for (int j = 0; j < 8; j++) {
                const int kg = kt * 64 + kslot * 8 + j;
                if (kg < NK) insert4u(v, packcand(sp[j], kg));
            }
            // merge sorted-4 lists across the 8 lanes of this row group
#pragma unroll
            for (int off = 4; off >= 1; off >>= 1) {
                unsigned long long o[4];
#pragma unroll
                for (int j = 0; j < 4; j++)
                    o[j] = __shfl_down_sync(0xffffffffu, v[j], off, 8);
                if (kslot < off) {
#pragma unroll
                    for (int j = 0; j < 4; j++) insert4u(v, o[j]);
                }
            }
            if (kslot == 0) {
                const int row_g = rt * 32 + row_l;
#pragma unroll
                for (int n = 0; n < 4; n++)
                    g_cand[side][row_g][kt * 4 + n] = v[n];
            }
        }
    } else {
        // ---- role B: query_projected = q @ Wqc + bqc (16 rows x 64 cols) ----
        const int b2 = b - 128;          // 0..191
        const int ct = b2 % 12;          // 64-col tile
        const int rt = b2 / 12;          // 16-row tile

#pragma unroll
        for (int k = 0; k < 8; k++) {
            const int idx = t + k * 256;
            const int r = idx >> 7, d = idx & 127;
            sqb[r][d] = g_q[(size_t)(rt * 16 + r) * KD + d];
        }
        __syncthreads();

        const int tx = t & 31;           // col pair
        const int ty = t >> 5;           // 8 row pairs
        const int col = ct * 64 + tx * 2;
        const int r0 = ty * 2;
        float a00 = 0.f, a01 = 0.f, a10 = 0.f, a11 = 0.f;
#pragma unroll 16
        for (int d = 0; d < KD; d++) {
            const float2 w = *(const float2*)&Wqc[(size_t)d * DDIM + col];
            const float q0 = sqb[r0 + 0][d];
            const float q1 = sqb[r0 + 1][d];
            a00 += q0 * w.x; a01 += q0 * w.y;
            a10 += q1 * w.x; a11 += q1 * w.y;
        }
        const float2 bb = *(const float2*)&bqc[col];
        const int grow = rt * 16 + r0;
        float* o = out + QP_OFF + (size_t)grow * DDIM + col;
        *(float2*)(o + 0 * DDIM) = make_float2(a00 + bb.x, a01 + bb.y);
        *(float2*)(o + 1 * DDIM) = make_float2(a10 + bb.x, a11 + bb.y);
    }
}

// ---------------------------------------------------------------------------
// KC: reduce 32 candidates per side, combine 4x4, write, gather
// grid 256 (one row), 256 threads
// ---------------------------------------------------------------------------
__global__ __launch_bounds__(256) void kc_topk_gather(
    const float* __restrict__ concepts,
    float* __restrict__ out)
{
    __shared__ unsigned long long s_top[2][TK];
    __shared__ int s_idx[TK];

    const int row  = blockIdx.x;
    const int t    = threadIdx.x;
    const int warp = t >> 5, lane = t & 31;

    // warps 0/1: per-side top-4 by 4-round u64 max extraction over 32 candidates
    if (warp < 2) {
        const int side = warp;
        unsigned long long c = g_cand[side][row][lane];
#pragma unroll
        for (int n = 0; n < TK; n++) {
            unsigned long long m = c;
#pragma unroll
            for (int off = 16; off >= 1; off >>= 1) {
                unsigned long long o = __shfl_xor_sync(0xffffffffu, m, off);
                if (o > m) m = o;
            }
            if (lane == 0) s_top[side][n] = m;
            if (c == m) c = 0ull;
        }
    }
    __syncthreads();

    // warp 2: 4x4 combine on 16 lanes, 4-round extraction
    if (warp == 2) {
        unsigned long long c = 0ull;
        if (lane < 16) {
            const unsigned long long r4 = s_top[0][lane >> 2];
            const unsigned long long c4 = s_top[1][lane & 3];
            const float sum = unpackval(r4) + unpackval(c4);
            const int flat  = unpackidx(r4) * NK + unpackidx(c4);
            c = packcand(sum, flat);
        }
#pragma unroll
        for (int n = 0; n < TK; n++) {
            unsigned long long m = c;
#pragma unroll
            for (int off = 16; off >= 1; off >>= 1) {
                unsigned long long o = __shfl_xor_sync(0xffffffffu, m, off);
                if (o > m) m = o;
            }
            if (lane == 0) {
                out[SC_OFF  + row * TK + n] = unpackval(m);
                const int fi = unpackidx(m);
                out[IDX_OFF + row * TK + n] = (float)fi;
                s_idx[n] = fi;
            }
            if (c == m) c = 0ull;
        }
    }
    __syncthreads();

    // gather 4 concept rows (4 x 192 float4), 3 per thread
#pragma unroll
    for (int k = 0; k < 3; k++) {
        const int i = t + k * 256;
        const int n = i / 192, j = i % 192;
        const int cid = s_idx[n];
        const float4 val = ((const float4*)concepts)[(size_t)cid * 192 + j];
        ((float4*)(out + OC_OFF))[(size_t)(row * TK + n) * 192 + j] = val;
    }
}

extern "C" void kernel_launch(void* const* d_in, const int* in_sizes, int n_in,
                              void* d_out, int out_size) {
    const float* regs     = (const float*)d_in[0];
    const float* row_keys = (const float*)d_in[1];
    const float* col_keys = (const float*)d_in[2];
    const float* concepts = (const float*)d_in[3];
    const float* gamma    = (const float*)d_in[4];
    const float* beta     = (const float*)d_in[5];
    const float* Wq       = (const float*)d_in[6];
    const float* bq       = (const float*)d_in[7];
    const float* Wqc      = (const float*)d_in[8];
    const float* bqc      = (const float*)d_in[9];
    float* out = (float*)d_out;

    k1_ln_q<<<dim3(8, 32), 256>>>(regs, gamma, beta, Wq, bq);
    kb_scores_qp<<<320, 256>>>(row_keys, col_keys, Wqc, bqc, out);
    kc_topk_gather<<<256, 256>>>(concepts, out);
}

// round 11
// speedup vs baseline: 1.8809x; 1.1099x over previous
#include <cuda_runtime.h>
#include <cstdint>

#define NROWS 256
#define DDIM  768
#define KD    128
#define NK    500
#define TK    4

// output layout (float32, reference return order)
#define OC_OFF  0
#define IDX_OFF 786432
#define SC_OFF  787456
#define QP_OFF  788480

#define NEG_INF (-3.402823466e38f)

__device__ float g_q[NROWS * KD];                      // queries
__device__ unsigned long long g_cand[2][NROWS][32];    // per (side,row): 8 tiles x top-4, packed

// ---- packed candidate: sortable float in high 32, ~idx in low 32 ----
__device__ __forceinline__ unsigned long long packcand(float f, int idx) {
    unsigned int b = __float_as_uint(f);
    unsigned int s = (b & 0x80000000u) ? ~b : (b | 0x80000000u);
    return ((unsigned long long)s << 32) | (unsigned int)(~idx);
}
__device__ __forceinline__ float unpackval(unsigned long long c) {
    unsigned int s = (unsigned int)(c >> 32);
    unsigned int b = (s & 0x80000000u) ? (s & 0x7FFFFFFFu) : ~s;
    return __uint_as_float(b);
}
__device__ __forceinline__ int unpackidx(unsigned long long c) {
    return (int)(~(unsigned int)(c & 0xFFFFFFFFu));
}

// sorted desc top-4 list of packed u64
__device__ __forceinline__ void insert4u(unsigned long long* v, unsigned long long x) {
    if (x <= v[3]) return;
    v[3] = x;
    if (v[3] > v[2]) { unsigned long long tt = v[3]; v[3] = v[2]; v[2] = tt; }
    if (v[2] > v[1]) { unsigned long long tt = v[2]; v[2] = v[1]; v[1] = tt; }
    if (v[1] > v[0]) { unsigned long long tt = v[1]; v[1] = v[0]; v[0] = tt; }
}

// ---------------------------------------------------------------------------
// K1: LN + Q = LN(x) @ Wq + bq
// grid (8 coltiles of 16, 32 rowtiles of 8), 256 threads
// __launch_bounds__(256, 2): 128-reg budget so the 8-wide LDG batch stays in flight
// ---------------------------------------------------------------------------
__global__ __launch_bounds__(256, 2) void k1_ln_q(
    const float* __restrict__ regs,
    const float* __restrict__ gamma,
    const float* __restrict__ beta,
    const float* __restrict__ Wq,
    const float* __restrict__ bq)
{
    __shared__ __align__(16) float sx[8][772];       // padded
    __shared__ __align__(16) float spart[8][8][16];  // [d8][row][col]
    __shared__ float s_mu[8], s_rs[8];

    const int t  = threadIdx.x;
    const int ct = blockIdx.x;     // 0..7  (16 cols)
    const int rt = blockIdx.y;     // 0..31 (8 rows)
    const int warp = t >> 5, lane = t & 31;

    // stage 8 input rows
    {
        const float4* src = (const float4*)(regs + (size_t)rt * 8 * DDIM);
#pragma unroll
        for (int k = 0; k < 6; k++) {
            const int idx = t + k * 256;            // 0..1535
            const int r = idx / 192, j = idx % 192;
            *(float4*)&sx[r][j * 4] = src[idx];
        }
    }
    __syncthreads();

    // LN stats: warp w handles row w, one pass (sum + sumsq)
    {
        float s = 0.f, q = 0.f;
        for (int i = lane; i < DDIM; i += 32) {
            const float xv = sx[warp][i];
            s += xv;
            q += xv * xv;
        }
#pragma unroll
        for (int o = 16; o; o >>= 1) {
            s += __shfl_xor_sync(0xffffffffu, s, o);
            q += __shfl_xor_sync(0xffffffffu, q, o);
        }
        if (lane == 0) {
            const float mu  = s * (1.0f / DDIM);
            const float var = q * (1.0f / DDIM) - mu * mu;
            s_mu[warp] = mu;
            s_rs[warp] = rsqrtf(var + 1e-5f);
        }
    }
    __syncthreads();

    // normalize in place
    {
        const float g0 = gamma[t], g1 = gamma[t + 256], g2 = gamma[t + 512];
        const float b0 = beta[t],  b1 = beta[t + 256],  b2 = beta[t + 512];
#pragma unroll
        for (int r = 0; r < 8; r++) {
            const float mu = s_mu[r], rs = s_rs[r];
            sx[r][t      ] = (sx[r][t      ] - mu) * rs * g0 + b0;
            sx[r][t + 256] = (sx[r][t + 256] - mu) * rs * g1 + b1;
            sx[r][t + 512] = (sx[r][t + 512] - mu) * rs * g2 + b2;
        }
    }
    __syncthreads();

    // GEMM: c4 = col quad, s -> (row, d-slice of 96)
    {
        const int c4 = t & 3;
        const int s  = t >> 2;
        const int r  = s & 7;
        const int d8 = s >> 3;
        const float* wp = Wq + (size_t)(d8 * 96) * KD + ct * 16 + c4 * 4;
        const float4* xp4 = (const float4*)&sx[r][d8 * 96];

        float ax = 0.f, ay = 0.f, az = 0.f, aw = 0.f;
#pragma unroll 1
        for (int g = 0; g < 12; g++) {
            // 8 independent global loads (MLP 8, now with register budget to match)
            float4 w0 = *(const float4*)(wp + (size_t)(g * 8 + 0) * KD);
            float4 w1 = *(const float4*)(wp + (size_t)(g * 8 + 1) * KD);
            float4 w2 = *(const float4*)(wp + (size_t)(g * 8 + 2) * KD);
            float4 w3 = *(const float4*)(wp + (size_t)(g * 8 + 3) * KD);
            float4 w4 = *(const float4*)(wp + (size_t)(g * 8 + 4) * KD);
            float4 w5 = *(const float4*)(wp + (size_t)(g * 8 + 5) * KD);
            float4 w6 = *(const float4*)(wp + (size_t)(g * 8 + 6) * KD);
            float4 w7 = *(const float4*)(wp + (size_t)(g * 8 + 7) * KD);
            const float4 xa = xp4[g * 2 + 0];
            const float4 xb = xp4[g * 2 + 1];

            ax += xa.x * w0.x; ay += xa.x * w0.y; az += xa.x * w0.z; aw += xa.x * w0.w;
            ax += xa.y * w1.x; ay += xa.y * w1.y; az += xa.y * w1.z; aw += xa.y * w1.w;
            ax += xa.z * w2.x; ay += xa.z * w2.y; az += xa.z * w2.z; aw += xa.z * w2.w;
            ax += xa.w * w3.x; ay += xa.w * w3.y; az += xa.w * w3.z; aw += xa.w * w3.w;
            ax += xb.x * w4.x; ay += xb.x * w4.y; az += xb.x * w4.z; aw += xb.x * w4.w;
            ax += xb.y * w5.x; ay += xb.y * w5.y; az += xb.y * w5.z; aw += xb.y * w5.w;
            ax += xb.z * w6.x; ay += xb.z * w6.y; az += xb.z * w6.z; aw += xb.z * w6.w;
            ax += xb.w * w7.x; ay += xb.w * w7.y; az += xb.w * w7.z; aw += xb.w * w7.w;
        }
        *(float4*)&spart[d8][r][c4 * 4] = make_float4(ax, ay, az, aw);
    }
    __syncthreads();

    if (t < 128) {
        const int r = t >> 4, c = t & 15;
        float sum = bq[ct * 16 + c];
#pragma unroll
        for (int k = 0; k < 8; k++) sum += spart[k][r][c];
        g_q[(size_t)(rt * 8 + r) * KD + ct * 16 + c] = sum;
    }
}

// ---------------------------------------------------------------------------
// KB: merged scores+candidate-topk (blocks 0..127) + query_projected (128..319)
// ---------------------------------------------------------------------------
__global__ __launch_bounds__(256, 2) void kb_scores_qp(
    const float* __restrict__ row_keys,
    const float* __restrict__ col_keys,
    const float* __restrict__ Wqc,
    const float* __restrict__ bqc,
    float* __restrict__ out)
{
    __shared__ float sk[64][66];   // role A: keys, d-major
    __shared__ float sq[32][64];   // role A: q halves
    __shared__ float ss[32][66];   // role A: scores (rows x keys), padded
    __shared__ float sqb[16][KD];  // role B

    const int t = threadIdx.x;
    const int b = blockIdx.x;
    const int warp = t >> 5, lane = t & 31;

    if (b < 128) {
        // ---- role A: scores = q_half @ keys^T  (64 keys x 32 rows) ----
        const int kt   = b & 7;          // 0..7
        const int rt   = (b >> 3) & 7;   // 0..7 (32 rows)
        const int side = b >> 6;         // 0..1
        const float* keys = side ? col_keys : row_keys;

        // stage keys transposed: sk[d][key]
        {
            const int d  = t & 63;
            const int k0 = t >> 6;       // 0..3
#pragma unroll
            for (int k = 0; k < 16; k++) {
                const int kl = k0 + k * 4;
                const int kg = kt * 64 + kl;
                sk[d][kl] = (kg < NK) ? keys[(size_t)kg * 64 + d] : 0.f;
            }
        }
        // stage q tile (32 rows x 64 half-dims)
#pragma unroll
        for (int k = 0; k < 8; k++) {
            const int idx = t + k * 256;
            const int r = idx >> 6, d = idx & 63;
            sq[r][d] = g_q[(size_t)(rt * 32 + r) * KD + side * 64 + d];
        }
        __syncthreads();

        const int kx = t & 31;           // key pair -> keys 2kx, 2kx+1
        const int rg = warp;             // rows 4rg..4rg+3
        float a0x = 0.f, a0y = 0.f, a1x = 0.f, a1y = 0.f;
        float a2x = 0.f, a2y = 0.f, a3x = 0.f, a3y = 0.f;
#pragma unroll 8
        for (int d = 0; d < 64; d++) {
            const float2 kv = *(const float2*)&sk[d][2 * kx];
            const float q0 = sq[4 * rg + 0][d];
            const float q1 = sq[4 * rg + 1][d];
            const float q2 = sq[4 * rg + 2][d];
            const float q3 = sq[4 * rg + 3][d];
            a0x += q0 * kv.x; a0y += q0 * kv.y;
            a1x += q1 * kv.x; a1y += q1 * kv.y;
            a2x += q2 * kv.x; a2y += q2 * kv.y;
            a3x += q3 * kv.x; a3y += q3 * kv.y;
        }
        // park scores in smem
        *(float2*)&ss[4 * rg + 0][2 * kx] = make_float2(a0x, a0y);
        *(float2*)&ss[4 * rg + 1][2 * kx] = make_float2(a1x, a1y);
        *(float2*)&ss[4 * rg + 2][2 * kx] = make_float2(a2x, a2y);
        *(float2*)&ss[4 * rg + 3][2 * kx] = make_float2(a3x, a3y);
        __syncthreads();

        // per-row top-4 extraction: warp w -> rows 4w..4w+3 (8 lanes per row)
        {
            const int rl    = lane >> 3;         // row within warp's group
            const int kslot = lane & 7;          // 8 keys per lane
            const int row_l = 4 * warp + rl;     // local row 0..31
            unsigned long long v[4] = {0ull, 0ull, 0ull, 0ull};
            const float* sp = &ss[row_l][kslot * 8];
#pragma unroll
            for (int j = 0; j < 8; j++) {
                const int kg = kt * 64 + kslot * 8 + j;
                if (kg < NK) insert4u(v, packcand(sp[j], kg));
            }
            // merge sorted-4 lists across the 8 lanes of this row group
#pragma unroll
            for (int off = 4; off >= 1; off >>= 1) {
                unsigned long long o[4];
#pragma unroll
                for (int j = 0; j < 4; j++)
                    o[j] = __shfl_down_sync(0xffffffffu, v[j], off, 8);
                if (kslot < off) {
#pragma unroll
                    for (int j = 0; j < 4; j++) insert4u(v, o[j]);
                }
            }
            if (kslot == 0) {
                const int row_g = rt * 32 + row_l;
#pragma unroll
                for (int n = 0; n < 4; n++)
                    g_cand[side][row_g][kt * 4 + n] = v[n];
            }
        }
    } else {
        // ---- role B: query_projected = q @ Wqc + bqc (16 rows x 64 cols) ----
        const int b2 = b - 128;          // 0..191
        const int ct = b2 % 12;          // 64-col tile
        const int rt = b2 / 12;          // 16-row tile

#pragma unroll
        for (int k = 0; k < 8; k++) {
            const int idx = t + k * 256;
            const int r = idx >> 7, d = idx & 127;
            sqb[r][d] = g_q[(size_t)(rt * 16 + r) * KD + d];
        }
        __syncthreads();

        const int tx = t & 31;           // col pair
        const int ty = t >> 5;           // 8 row pairs
        const int col = ct * 64 + tx * 2;
        const int r0 = ty * 2;
        float a00 = 0.f, a01 = 0.f, a10 = 0.f, a11 = 0.f;
#pragma unroll 16
        for (int d = 0; d < KD; d++) {
            const float2 w = *(const float2*)&Wqc[(size_t)d * DDIM + col];
            const float q0 = sqb[r0 + 0][d];
            const float q1 = sqb[r0 + 1][d];
            a00 += q0 * w.x; a01 += q0 * w.y;
            a10 += q1 * w.x; a11 += q1 * w.y;
        }
        const float2 bb = *(const float2*)&bqc[col];
        const int grow = rt * 16 + r0;
        float* o = out + QP_OFF + (size_t)grow * DDIM + col;
        *(float2*)(o + 0 * DDIM) = make_float2(a00 + bb.x, a01 + bb.y);
        *(float2*)(o + 1 * DDIM) = make_float2(a10 + bb.x, a11 + bb.y);
    }
}

// ---------------------------------------------------------------------------
// KC: reduce 32 candidates per side, combine 4x4, write, gather
// grid 256 (one row), 256 threads
// ---------------------------------------------------------------------------
__global__ __launch_bounds__(256) void kc_topk_gather(
    const float* __restrict__ concepts,
    float* __restrict__ out)
{
    __shared__ unsigned long long s_top[2][TK];
    __shared__ int s_idx[TK];

    const int row  = blockIdx.x;
    const int t    = threadIdx.x;
    const int warp = t >> 5, lane = t & 31;

    // warps 0/1: per-side top-4 by 4-round u64 max extraction over 32 candidates
    if (warp < 2) {
        const int side = warp;
        unsigned long long c = g_cand[side][row][lane];
#pragma unroll
        for (int n = 0; n < TK; n++) {
            unsigned long long m = c;
#pragma unroll
            for (int off = 16; off >= 1; off >>= 1) {
                unsigned long long o = __shfl_xor_sync(0xffffffffu, m, off);
                if (o > m) m = o;
            }
            if (lane == 0) s_top[side][n] = m;
            if (c == m) c = 0ull;
        }
    }
    __syncthreads();

    // warp 2: 4x4 combine on 16 lanes, 4-round extraction
    if (warp == 2) {
        unsigned long long c = 0ull;
        if (lane < 16) {
            const unsigned long long r4 = s_top[0][lane >> 2];
            const unsigned long long c4 = s_top[1][lane & 3];
            const float sum = unpackval(r4) + unpackval(c4);
            const int flat  = unpackidx(r4) * NK + unpackidx(c4);
            c = packcand(sum, flat);
        }
#pragma unroll
        for (int n = 0; n < TK; n++) {
            unsigned long long m = c;
#pragma unroll
            for (int off = 16; off >= 1; off >>= 1) {
                unsigned long long o = __shfl_xor_sync(0xffffffffu, m, off);
                if (o > m) m = o;
            }
            if (lane == 0) {
                out[SC_OFF  + row * TK + n] = unpackval(m);
                const int fi = unpackidx(m);
                out[IDX_OFF + row * TK + n] = (float)fi;
                s_idx[n] = fi;
            }
            if (c == m) c = 0ull;
        }
    }
    __syncthreads();

    // gather 4 concept rows (4 x 192 float4), 3 per thread
#pragma unroll
    for (int k = 0; k < 3; k++) {
        const int i = t + k * 256;
        const int n = i / 192, j = i % 192;
        const int cid = s_idx[n];
        const float4 val = ((const float4*)concepts)[(size_t)cid * 192 + j];
        ((float4*)(out + OC_OFF))[(size_t)(row * TK + n) * 192 + j] = val;
    }
}

extern "C" void kernel_launch(void* const* d_in, const int* in_sizes, int n_in,
                              void* d_out, int out_size) {
    const float* regs     = (const float*)d_in[0];
    const float* row_keys = (const float*)d_in[1];
    const float* col_keys = (const float*)d_in[2];
    const float* concepts = (const float*)d_in[3];
    const float* gamma    = (const float*)d_in[4];
    const float* beta     = (const float*)d_in[5];
    const float* Wq       = (const float*)d_in[6];
    const float* bq       = (const float*)d_in[7];
    const float* Wqc      = (const float*)d_in[8];
    const float* bqc      = (const float*)d_in[9];
    float* out = (float*)d_out;

    k1_ln_q<<<dim3(8, 32), 256>>>(regs, gamma, beta, Wq, bq);
    kb_scores_qp<<<320, 256>>>(row_keys, col_keys, Wqc, bqc, out);
    kc_topk_gather<<<256, 256>>>(concepts, out);
}